// round 9
// baseline (speedup 1.0000x reference)
#include <cuda_runtime.h>
#include <cuda_bf16.h>
#include <math.h>
#include <stdint.h>

// ---------------- problem constants -------------------------------------------
#define BTOK   4096
#define DIN    1024
#define DHID   4096
#define DOUT   1024
#define NE     8
#define TOPK   2
#define MAXROWS (BTOK * TOPK)          // 8192 grouped rows, always exact
#define BM     128
#define BN     128
#define BK     32
#define MAXTILES (MAXROWS / BM + NE)   // 72 worst-case m-tiles

#define LDE    40                      // smem lead dim in bf16 elems (80 B)
#define LDB    80                      // in bytes

// dynamic smem: per buffer Ah|Al|Bh|Bl, each BM*LDE uint16 = 10240 B
#define REG_B   10240
#define BUF_B   (4 * REG_B)            // 40960 B
#define SMEM_B  (2 * BUF_B)            // 81920 B

#define RT_THREADS 256
#define TOK_PER_TH (BTOK / RT_THREADS) // 16

// ---------------- device scratch (device-code-only access!) --------------------
__device__ uint32_t g_h_hi[MAXROWS * (size_t)(DHID / 2)]; // bf16x2 hidden hi
__device__ uint32_t g_h_lo[MAXROWS * (size_t)(DHID / 2)]; // bf16x2 hidden lo
__device__ float    g_y[MAXROWS * (size_t)DOUT];
__device__ float    g_gates[BTOK * NE];
__device__ float    g_topw[BTOK * TOPK];
__device__ int      g_topi[BTOK * TOPK];
__device__ int      g_counts[NE];
__device__ int      g_token_of_row[MAXROWS];
__device__ int      g_row_of[BTOK * TOPK];

// ---------------- helpers -------------------------------------------------------
__device__ __forceinline__ uint32_t smem_u32(const void* p) {
    uint32_t a;
    asm("{ .reg .u64 t; cvta.to.shared.u64 t, %1; cvt.u32.u64 %0, t; }"
        : "=r"(a) : "l"(p));
    return a;
}

__device__ __forceinline__ void ldsm4(uint32_t* r, uint32_t addr) {
    asm volatile("ldmatrix.sync.aligned.m8n8.x4.shared.b16 {%0,%1,%2,%3}, [%4];"
                 : "=r"(r[0]), "=r"(r[1]), "=r"(r[2]), "=r"(r[3]) : "r"(addr));
}

__device__ __forceinline__ void mma_bf16(float* c, const uint32_t* a,
                                         uint32_t b0, uint32_t b1) {
    asm volatile(
        "mma.sync.aligned.m16n8k16.row.col.f32.bf16.bf16.f32 "
        "{%0,%1,%2,%3}, {%4,%5,%6,%7}, {%8,%9}, {%0,%1,%2,%3};"
        : "+f"(c[0]), "+f"(c[1]), "+f"(c[2]), "+f"(c[3])
        : "r"(a[0]), "r"(a[1]), "r"(a[2]), "r"(a[3]), "r"(b0), "r"(b1));
}

#define STS128(addr, r0, r1, r2, r3) \
    asm volatile("st.shared.v4.b32 [%0], {%1, %2, %3, %4};" \
                 :: "r"(addr), "r"(r0), "r"(r1), "r"(r2), "r"(r3))

__device__ __forceinline__ uint32_t bf2u(__nv_bfloat162 h) {
    return *reinterpret_cast<uint32_t*>(&h);
}

// split two fp32 into packed bf16x2 hi and lo words (lo = residual)
__device__ __forceinline__ void split2(float a, float b, uint32_t& hi, uint32_t& lo) {
    __nv_bfloat162 hp = __floats2bfloat162_rn(a, b);
    float la = a - __bfloat162float(hp.x);
    float lb = b - __bfloat162float(hp.y);
    __nv_bfloat162 lp = __floats2bfloat162_rn(la, lb);
    hi = bf2u(hp);
    lo = bf2u(lp);
}

// ---------------- gating / routing / loss --------------------------------------

__global__ void gating_kernel(const float* __restrict__ x,
                              const float* __restrict__ Wg,
                              const float* __restrict__ bg) {
    int gwarp = (blockIdx.x * blockDim.x + threadIdx.x) >> 5;
    int lane  = threadIdx.x & 31;
    if (gwarp >= BTOK) return;
    const float* xr = x + (size_t)gwarp * DIN;

    float acc[NE];
#pragma unroll
    for (int e = 0; e < NE; e++) acc[e] = 0.f;

    for (int i = lane; i < DIN; i += 32) {
        float xv = xr[i];
        const float4* wg4 = (const float4*)(Wg + (size_t)i * NE);
        float4 w0 = wg4[0];
        float4 w1 = wg4[1];
        acc[0] += xv * w0.x; acc[1] += xv * w0.y;
        acc[2] += xv * w0.z; acc[3] += xv * w0.w;
        acc[4] += xv * w1.x; acc[5] += xv * w1.y;
        acc[6] += xv * w1.z; acc[7] += xv * w1.w;
    }
#pragma unroll
    for (int e = 0; e < NE; e++)
#pragma unroll
        for (int o = 16; o > 0; o >>= 1)
            acc[e] += __shfl_xor_sync(0xffffffffu, acc[e], o);

    if (lane == 0) {
        float logit[NE];
#pragma unroll
        for (int e = 0; e < NE; e++) logit[e] = acc[e] + bg[e];

        float mx = logit[0];
#pragma unroll
        for (int e = 1; e < NE; e++) mx = fmaxf(mx, logit[e]);
        float s = 0.f, ex[NE];
#pragma unroll
        for (int e = 0; e < NE; e++) { ex[e] = expf(logit[e] - mx); s += ex[e]; }
        float inv = 1.f / s;
#pragma unroll
        for (int e = 0; e < NE; e++) g_gates[gwarp * NE + e] = ex[e] * inv;

        int i0 = 0;
#pragma unroll
        for (int e = 1; e < NE; e++) if (logit[e] > logit[i0]) i0 = e;
        int i1 = -1;
#pragma unroll
        for (int e = 0; e < NE; e++)
            if (e != i0 && (i1 < 0 || logit[e] > logit[i1])) i1 = e;

        float w0 = 1.f / (1.f + expf(logit[i1] - logit[i0]));
        g_topi[gwarp * 2 + 0] = i0;
        g_topi[gwarp * 2 + 1] = i1;
        g_topw[gwarp * 2 + 0] = w0;
        g_topw[gwarp * 2 + 1] = 1.f - w0;
    }
}

__global__ void route_kernel() {
    __shared__ int hist[RT_THREADS][NE];
    __shared__ int offs_sh[NE];
    __shared__ int counts_sh[NE];
    int tid = threadIdx.x;

    int h[NE];
#pragma unroll
    for (int e = 0; e < NE; e++) h[e] = 0;
    int t0 = tid * TOK_PER_TH;
    for (int i = 0; i < TOK_PER_TH; i++) {
        int t = t0 + i;
        h[g_topi[t * 2 + 0]]++;
        h[g_topi[t * 2 + 1]]++;
    }
#pragma unroll
    for (int e = 0; e < NE; e++) hist[tid][e] = h[e];
    __syncthreads();

    if (tid < NE) {
        int e = tid, s = 0;
        for (int j = 0; j < RT_THREADS; j++) {
            int v = hist[j][e];
            hist[j][e] = s;
            s += v;
        }
        counts_sh[e] = s;
        g_counts[e]  = s;
    }
    __syncthreads();

    if (tid == 0) {
        int off = 0;
        for (int e = 0; e < NE; e++) { offs_sh[e] = off; off += counts_sh[e]; }
    }
    __syncthreads();

    int base[NE];
#pragma unroll
    for (int e = 0; e < NE; e++) base[e] = offs_sh[e] + hist[tid][e];

    for (int i = 0; i < TOK_PER_TH; i++) {
        int t = t0 + i;
#pragma unroll
        for (int k = 0; k < TOPK; k++) {
            int e   = g_topi[t * 2 + k];
            int row = base[e]++;
            g_token_of_row[row] = t;
            g_row_of[t * 2 + k] = row;
        }
    }
}

// Fused per-expert usage mean + load-balance loss (single block, deterministic).
__global__ void usage_loss_kernel(float* __restrict__ out, int out_size) {
    __shared__ float s[256][NE];
    int tid = threadIdx.x;
    float acc[NE];
#pragma unroll
    for (int e = 0; e < NE; e++) acc[e] = 0.f;
    for (int t = tid; t < BTOK; t += 256) {
        const float* g = g_gates + (size_t)t * NE;
#pragma unroll
        for (int e = 0; e < NE; e++) acc[e] += g[e];
    }
#pragma unroll
    for (int e = 0; e < NE; e++) s[tid][e] = acc[e];
    __syncthreads();
    if (tid == 0) {
        float loss = 0.f;
        for (int e = 0; e < NE; e++) {
            float u = 0.f;
            for (int j = 0; j < 256; j++) u += s[j][e];
            u /= (float)BTOK;
            loss += u * u;
        }
        if (out_size > BTOK * DOUT) out[BTOK * DOUT] = (float)NE * loss;
    }
}

// ---------------- grouped GEMM via mma.sync (HMMA), split-bf16 3-pass -----------
// Double-buffered smem: one __syncthreads per K-chunk; STS(i+1) overlaps MMA(i).
// STAGE=1: A = x (gathered fp32, split on load) -> g_h hi/lo (bf16x2), ReLU.
// STAGE=2: A = g_h hi/lo (pre-split)            -> g_y (fp32).
template <int KD, int ND, int STAGE>
__global__ void __launch_bounds__(256)
moe_gemm_mma(const float* __restrict__ Aext,
             const float* __restrict__ W,
             const float* __restrict__ bias) {
    int t = blockIdx.x;

    int e = 0, grow0 = 0, rows = 0;
    {
        int tileacc = 0, off = 0;
        bool found = false;
#pragma unroll
        for (int ee = 0; ee < NE; ee++) {
            int c  = g_counts[ee];
            int nt = (c + BM - 1) / BM;
            if (!found && t < tileacc + nt) {
                found = true;
                e     = ee;
                int rb = (t - tileacc) * BM;
                grow0 = off + rb;
                rows  = min(BM, c - rb);
            }
            tileacc += nt;
            off     += c;
        }
        if (!found) return;
    }
    int n0 = blockIdx.y * BN;

    extern __shared__ __align__(16) uint16_t dynsmem[];
    uint32_t sbase = smem_u32(dynsmem);
    uint32_t Ah_b[2], Al_b[2], Bh_b[2], Bl_b[2];
#pragma unroll
    for (int b = 0; b < 2; b++) {
        Ah_b[b] = sbase + b * BUF_B;
        Al_b[b] = Ah_b[b] + REG_B;
        Bh_b[b] = Ah_b[b] + 2 * REG_B;
        Bl_b[b] = Ah_b[b] + 3 * REG_B;
    }

    int tid = threadIdx.x, wid = tid >> 5, lane = tid & 31;
    int warp_m = wid & 3;        // 0..3 -> m offset *32
    int warp_n = wid >> 2;       // 0..1 -> n offset *64

    // ---- global loader mapping ----
    int arow = tid >> 1, khalf = tid & 1;
    bool rvalid = arow < rows;
    const float* Arow = nullptr;
    const uint4 *Ah4 = nullptr, *Al4 = nullptr;
    if (STAGE == 1) {
        int tok = rvalid ? g_token_of_row[grow0 + arow] : 0;
        Arow = Aext + (size_t)tok * KD;
    } else {
        size_t rb = (size_t)(rvalid ? (grow0 + arow) : 0) * (KD / 2) / 4;
        Ah4 = ((const uint4*)g_h_hi) + rb;
        Al4 = ((const uint4*)g_h_lo) + rb;
    }
    int bn_l = tid & 127, bkq = (tid >> 7) * 16;
    const float* Wp = W + (size_t)e * KD * ND + n0 + bn_l;

    // ---- ldmatrix address bases ----
    int alr = lane & 15, alc = lane >> 4;
    uint32_t a_off = (uint32_t)(warp_m * 32 + alr) * LDB + (uint32_t)alc * 16;
    int bnr = (lane & 7) + ((lane >> 4) & 1) * 8;
    int bkr = ((lane >> 3) & 1) * 8;
    uint32_t b_off = (uint32_t)(warp_n * 64 + bnr) * LDB + (uint32_t)bkr * 2;

    float acc[2][8][4];
#pragma unroll
    for (int i = 0; i < 2; i++)
#pragma unroll
        for (int j = 0; j < 8; j++)
#pragma unroll
            for (int q = 0; q < 4; q++) acc[i][j][q] = 0.f;

    // staged global data
    float4 av[4];
    uint4  ahv[2], alv[2];
    float  bv[16];
#pragma unroll
    for (int q = 0; q < 4; q++) av[q] = make_float4(0, 0, 0, 0);
    ahv[0] = ahv[1] = alv[0] = alv[1] = make_uint4(0, 0, 0, 0);

    const int NCH = KD / BK;

    auto ldg_chunk = [&](int it) {
        int k0 = it * BK;
        if (STAGE == 1) {
            if (rvalid) {
                const float4* p = (const float4*)(Arow + k0 + khalf * 16);
#pragma unroll
                for (int q = 0; q < 4; q++) av[q] = p[q];
            }
        } else {
            int idx = (k0 >> 3) + khalf * 2;
            if (rvalid) {
                ahv[0] = Ah4[idx]; ahv[1] = Ah4[idx + 1];
                alv[0] = Al4[idx]; alv[1] = Al4[idx + 1];
            }
        }
#pragma unroll
        for (int j = 0; j < 16; j++)
            bv[j] = Wp[(size_t)(k0 + bkq + j) * ND];
    };

    auto sts_chunk = [&](int buf) {
        uint32_t hi[8], lo[8];
        if (STAGE == 1) {
            split2(av[0].x, av[0].y, hi[0], lo[0]);
            split2(av[0].z, av[0].w, hi[1], lo[1]);
            split2(av[1].x, av[1].y, hi[2], lo[2]);
            split2(av[1].z, av[1].w, hi[3], lo[3]);
            split2(av[2].x, av[2].y, hi[4], lo[4]);
            split2(av[2].z, av[2].w, hi[5], lo[5]);
            split2(av[3].x, av[3].y, hi[6], lo[6]);
            split2(av[3].z, av[3].w, hi[7], lo[7]);
        } else {
            hi[0] = ahv[0].x; hi[1] = ahv[0].y; hi[2] = ahv[0].z; hi[3] = ahv[0].w;
            hi[4] = ahv[1].x; hi[5] = ahv[1].y; hi[6] = ahv[1].z; hi[7] = ahv[1].w;
            lo[0] = alv[0].x; lo[1] = alv[0].y; lo[2] = alv[0].z; lo[3] = alv[0].w;
            lo[4] = alv[1].x; lo[5] = alv[1].y; lo[6] = alv[1].z; lo[7] = alv[1].w;
        }
        uint32_t aaddr = (uint32_t)arow * LDB + (uint32_t)khalf * 32;
        STS128(Ah_b[buf] + aaddr,      hi[0], hi[1], hi[2], hi[3]);
        STS128(Ah_b[buf] + aaddr + 16, hi[4], hi[5], hi[6], hi[7]);
        STS128(Al_b[buf] + aaddr,      lo[0], lo[1], lo[2], lo[3]);
        STS128(Al_b[buf] + aaddr + 16, lo[4], lo[5], lo[6], lo[7]);

        uint32_t bhi[8], blo[8];
#pragma unroll
        for (int q = 0; q < 8; q++)
            split2(bv[2 * q], bv[2 * q + 1], bhi[q], blo[q]);
        uint32_t baddr = (uint32_t)bn_l * LDB + (uint32_t)bkq * 2;
        STS128(Bh_b[buf] + baddr,      bhi[0], bhi[1], bhi[2], bhi[3]);
        STS128(Bh_b[buf] + baddr + 16, bhi[4], bhi[5], bhi[6], bhi[7]);
        STS128(Bl_b[buf] + baddr,      blo[0], blo[1], blo[2], blo[3]);
        STS128(Bl_b[buf] + baddr + 16, blo[4], blo[5], blo[6], blo[7]);
    };

    // prologue: chunk 0 into buffer 0
    ldg_chunk(0);
    sts_chunk(0);
    __syncthreads();

    for (int it = 0; it < NCH; it++) {
        int cur = it & 1;
        if (it + 1 < NCH) ldg_chunk(it + 1);

        // ---- mma on buffer cur: 2 k-steps x 3 passes ----
#pragma unroll
        for (int h = 0; h < 2; h++) {
            uint32_t fAh[2][4], fAl[2][4];
#pragma unroll
            for (int mi = 0; mi < 2; mi++) {
                uint32_t ad = a_off + (uint32_t)mi * (16 * LDB) + (uint32_t)h * 32;
                ldsm4(fAh[mi], Ah_b[cur] + ad);
                ldsm4(fAl[mi], Al_b[cur] + ad);
            }
            uint32_t fBh[4][4], fBl[4][4];
#pragma unroll
            for (int n2 = 0; n2 < 4; n2++) {
                uint32_t bd = b_off + (uint32_t)n2 * (16 * LDB) + (uint32_t)h * 32;
                ldsm4(fBh[n2], Bh_b[cur] + bd);
                ldsm4(fBl[n2], Bl_b[cur] + bd);
            }
#pragma unroll
            for (int mi = 0; mi < 2; mi++)
#pragma unroll
                for (int n2 = 0; n2 < 4; n2++) {
                    mma_bf16(acc[mi][2 * n2],     fAh[mi], fBh[n2][0], fBh[n2][1]);
                    mma_bf16(acc[mi][2 * n2 + 1], fAh[mi], fBh[n2][2], fBh[n2][3]);
                    mma_bf16(acc[mi][2 * n2],     fAh[mi], fBl[n2][0], fBl[n2][1]);
                    mma_bf16(acc[mi][2 * n2 + 1], fAh[mi], fBl[n2][2], fBl[n2][3]);
                    mma_bf16(acc[mi][2 * n2],     fAl[mi], fBh[n2][0], fBh[n2][1]);
                    mma_bf16(acc[mi][2 * n2 + 1], fAl[mi], fBh[n2][2], fBh[n2][3]);
                }
        }

        if (it + 1 < NCH) sts_chunk(cur ^ 1);
        __syncthreads();
    }

    // ---- epilogue ----
#pragma unroll
    for (int mi = 0; mi < 2; mi++) {
        int m_lo = warp_m * 32 + mi * 16 + (lane >> 2);
#pragma unroll
        for (int ni = 0; ni < 8; ni++) {
            int ncol = warp_n * 64 + ni * 8 + 2 * (lane & 3);
            float b0 = bias[(size_t)e * ND + n0 + ncol];
            float b1 = bias[(size_t)e * ND + n0 + ncol + 1];
#pragma unroll
            for (int half = 0; half < 2; half++) {
                int m = m_lo + half * 8;
                if (m < rows) {
                    float v0 = acc[mi][ni][2 * half]     + b0;
                    float v1 = acc[mi][ni][2 * half + 1] + b1;
                    size_t grow = (size_t)(grow0 + m);
                    if (STAGE == 1) {
                        v0 = fmaxf(v0, 0.f);
                        v1 = fmaxf(v1, 0.f);
                        uint32_t hw, lw;
                        split2(v0, v1, hw, lw);
                        size_t hidx = grow * (ND / 2) + (size_t)(n0 + ncol) / 2;
                        g_h_hi[hidx] = hw;
                        g_h_lo[hidx] = lw;
                    } else {
                        float* cp = g_y + grow * ND + n0 + ncol;
                        cp[0] = v0;
                        cp[1] = v1;
                    }
                }
            }
        }
    }
}

// out[t] = w0 * y[row0] + w1 * y[row1]
__global__ void combine_kernel(float* __restrict__ out) {
    int t = blockIdx.x;
    int r0 = g_row_of[t * 2 + 0];
    int r1 = g_row_of[t * 2 + 1];
    float w0 = g_topw[t * 2 + 0];
    float w1 = g_topw[t * 2 + 1];
    const float4* y0 = (const float4*)(g_y + (size_t)r0 * DOUT);
    const float4* y1 = (const float4*)(g_y + (size_t)r1 * DOUT);
    float4* o = (float4*)(out + (size_t)t * DOUT);
    for (int j = threadIdx.x; j < DOUT / 4; j += blockDim.x) {
        float4 a = y0[j], b = y1[j];
        float4 r;
        r.x = w0 * a.x + w1 * b.x;
        r.y = w0 * a.y + w1 * b.y;
        r.z = w0 * a.z + w1 * b.z;
        r.w = w0 * a.w + w1 * b.w;
        o[j] = r;
    }
}

// ---------------- launch ---------------------------------------------------------

extern "C" void kernel_launch(void* const* d_in, const int* in_sizes, int n_in,
                              void* d_out, int out_size) {
    const float *x = 0, *Wg = 0, *bg = 0, *W1 = 0, *b1 = 0, *W2 = 0, *b2 = 0;
    for (int i = 0; i < n_in; i++) {
        const float* p = (const float*)d_in[i];
        switch (in_sizes[i]) {
            case BTOK * DIN:        x  = p; break;                        // 4194304
            case NE:                bg = p; break;                        // 8
            case NE * DHID:         b1 = p; break;                        // 32768
            case NE * DIN * DHID:   if (!W1) W1 = p; else W2 = p; break;  // 33554432
            case DIN * NE:          if (!Wg) Wg = p; else b2 = p; break;  // 8192
            default: break;
        }
    }
    if (!(x && Wg && bg && W1 && b1 && W2 && b2)) {
        x  = (const float*)d_in[0]; Wg = (const float*)d_in[1];
        bg = (const float*)d_in[2]; W1 = (const float*)d_in[3];
        b1 = (const float*)d_in[4]; W2 = (const float*)d_in[5];
        b2 = (const float*)d_in[6];
    }
    float* out = (float*)d_out;

    cudaFuncSetAttribute(moe_gemm_mma<DIN, DHID, 1>,
                         cudaFuncAttributeMaxDynamicSharedMemorySize, SMEM_B);
    cudaFuncSetAttribute(moe_gemm_mma<DHID, DOUT, 2>,
                         cudaFuncAttributeMaxDynamicSharedMemorySize, SMEM_B);

    gating_kernel<<<BTOK / 8, 256>>>(x, Wg, bg);          // launch 1
    route_kernel<<<1, RT_THREADS>>>();                    // launch 2
    usage_loss_kernel<<<1, 256>>>(out, out_size);         // launch 3

    moe_gemm_mma<DIN, DHID, 1>                            // launch 4 (ncu target)
        <<<dim3(MAXTILES, DHID / BN), 256, SMEM_B>>>(x, W1, b1);
    moe_gemm_mma<DHID, DOUT, 2>                           // launch 5
        <<<dim3(MAXTILES, DOUT / BN), 256, SMEM_B>>>(nullptr, W2, b2);

    combine_kernel<<<BTOK, 256>>>(out);                   // launch 6
}

// round 10
// speedup vs baseline: 1.4402x; 1.4402x over previous
#include <cuda_runtime.h>
#include <cuda_bf16.h>
#include <math.h>
#include <stdint.h>

// ---------------- problem constants -------------------------------------------
#define BTOK   4096
#define DIN    1024
#define DHID   4096
#define DOUT   1024
#define NE     8
#define TOPK   2
#define MAXROWS (BTOK * TOPK)          // 8192 grouped rows, always exact
#define BM     128
#define BN     128
#define BK     32
#define MAXTILES (MAXROWS / BM + NE)   // 72 worst-case m-tiles

#define RT_THREADS 256
#define TOK_PER_TH (BTOK / RT_THREADS) // 16

// ---------------- smem tile geometry --------------------------------------------
#define A_STRIDE 80                     // bytes per A row: 32 bf16 (64B) + 16B pad
#define B_STRIDE 272                    // bytes per B k-row: 128 bf16 (256B) + 16B pad
#define A_REG (BM * A_STRIDE)           // 10240
#define B_REG (BK * B_STRIDE)           // 8704
#define BUF_BYTES (2 * A_REG + 2 * B_REG)   // 37888: A_hi|A_lo|B_hi|B_lo
#define SMEM_TOTAL (2 * BUF_BYTES)          // 75776

// split-pair counts for the fused conversion kernel
#define XPAIRS (BTOK * DIN / 2)              // 2,097,152
#define WPAIRS (NE * DIN * DHID / 2)         // 16,777,216
#define ALLPAIRS (XPAIRS + 2 * WPAIRS)       // 35,651,584

// ---------------- device scratch (device-code-only access!) --------------------
__device__ uint32_t g_x_hi[BTOK * (size_t)(DIN / 2)];
__device__ uint32_t g_x_lo[BTOK * (size_t)(DIN / 2)];
__device__ uint32_t g_w1_hi[(size_t)NE * DIN * DHID / 2];
__device__ uint32_t g_w1_lo[(size_t)NE * DIN * DHID / 2];
__device__ uint32_t g_w2_hi[(size_t)NE * DHID * DOUT / 2];
__device__ uint32_t g_w2_lo[(size_t)NE * DHID * DOUT / 2];
__device__ uint32_t g_h_hi[MAXROWS * (size_t)(DHID / 2)];
__device__ uint32_t g_h_lo[MAXROWS * (size_t)(DHID / 2)];
__device__ float    g_y[MAXROWS * (size_t)DOUT];
__device__ float    g_gates[BTOK * NE];
__device__ float    g_topw[BTOK * TOPK];
__device__ int      g_topi[BTOK * TOPK];
__device__ int      g_counts[NE];
__device__ int      g_token_of_row[MAXROWS];
__device__ int      g_row_of[BTOK * TOPK];

// ---------------- helpers -------------------------------------------------------
__device__ __forceinline__ uint32_t smem_u32(const void* p) {
    uint32_t a;
    asm("{ .reg .u64 t; cvta.to.shared.u64 t, %1; cvt.u32.u64 %0, t; }"
        : "=r"(a) : "l"(p));
    return a;
}

__device__ __forceinline__ void ldsm4(uint32_t* r, uint32_t addr) {
    asm volatile("ldmatrix.sync.aligned.m8n8.x4.shared.b16 {%0,%1,%2,%3}, [%4];"
                 : "=r"(r[0]), "=r"(r[1]), "=r"(r[2]), "=r"(r[3]) : "r"(addr));
}

__device__ __forceinline__ void ldsm4t(uint32_t* r, uint32_t addr) {
    asm volatile("ldmatrix.sync.aligned.m8n8.x4.trans.shared.b16 {%0,%1,%2,%3}, [%4];"
                 : "=r"(r[0]), "=r"(r[1]), "=r"(r[2]), "=r"(r[3]) : "r"(addr));
}

__device__ __forceinline__ void mma_bf16(float* c, const uint32_t* a,
                                         uint32_t b0, uint32_t b1) {
    asm volatile(
        "mma.sync.aligned.m16n8k16.row.col.f32.bf16.bf16.f32 "
        "{%0,%1,%2,%3}, {%4,%5,%6,%7}, {%8,%9}, {%0,%1,%2,%3};"
        : "+f"(c[0]), "+f"(c[1]), "+f"(c[2]), "+f"(c[3])
        : "r"(a[0]), "r"(a[1]), "r"(a[2]), "r"(a[3]), "r"(b0), "r"(b1));
}

__device__ __forceinline__ void cp16(uint32_t dst, const void* src) {
    asm volatile("cp.async.cg.shared.global [%0], [%1], 16;"
                 :: "r"(dst), "l"(src));
}
#define CP_COMMIT() asm volatile("cp.async.commit_group;" ::: "memory")
#define CP_WAIT1()  asm volatile("cp.async.wait_group 1;" ::: "memory")
#define CP_WAIT0()  asm volatile("cp.async.wait_group 0;" ::: "memory")

__device__ __forceinline__ uint32_t bf2u(__nv_bfloat162 h) {
    return *reinterpret_cast<uint32_t*>(&h);
}

// split two fp32 into packed bf16x2 hi and lo words (lo = residual)
__device__ __forceinline__ void split2(float a, float b, uint32_t& hi, uint32_t& lo) {
    __nv_bfloat162 hp = __floats2bfloat162_rn(a, b);
    float la = a - __bfloat162float(hp.x);
    float lb = b - __bfloat162float(hp.y);
    __nv_bfloat162 lp = __floats2bfloat162_rn(la, lb);
    hi = bf2u(hp);
    lo = bf2u(lp);
}

// ---------------- fused split: x, W1, W2 -> bf16 hi/lo --------------------------
__global__ void split_all_kernel(const float* __restrict__ x,
                                 const float* __restrict__ W1,
                                 const float* __restrict__ W2) {
    size_t p = (size_t)blockIdx.x * blockDim.x + threadIdx.x;
    if (p >= ALLPAIRS) return;
    const float* src;
    uint32_t *dh, *dl;
    size_t q;
    if (p < XPAIRS)                 { q = p;                src = x;  dh = g_x_hi;  dl = g_x_lo;  }
    else if (p < XPAIRS + WPAIRS)   { q = p - XPAIRS;        src = W1; dh = g_w1_hi; dl = g_w1_lo; }
    else                            { q = p - XPAIRS - WPAIRS; src = W2; dh = g_w2_hi; dl = g_w2_lo; }
    float2 v = ((const float2*)src)[q];
    uint32_t hi, lo;
    split2(v.x, v.y, hi, lo);
    dh[q] = hi;
    dl[q] = lo;
}

// ---------------- gating / routing / loss --------------------------------------

__global__ void gating_kernel(const float* __restrict__ x,
                              const float* __restrict__ Wg,
                              const float* __restrict__ bg) {
    int gwarp = (blockIdx.x * blockDim.x + threadIdx.x) >> 5;
    int lane  = threadIdx.x & 31;
    if (gwarp >= BTOK) return;
    const float* xr = x + (size_t)gwarp * DIN;

    float acc[NE];
#pragma unroll
    for (int e = 0; e < NE; e++) acc[e] = 0.f;

    for (int i = lane; i < DIN; i += 32) {
        float xv = xr[i];
        const float4* wg4 = (const float4*)(Wg + (size_t)i * NE);
        float4 w0 = wg4[0];
        float4 w1 = wg4[1];
        acc[0] += xv * w0.x; acc[1] += xv * w0.y;
        acc[2] += xv * w0.z; acc[3] += xv * w0.w;
        acc[4] += xv * w1.x; acc[5] += xv * w1.y;
        acc[6] += xv * w1.z; acc[7] += xv * w1.w;
    }
#pragma unroll
    for (int e = 0; e < NE; e++)
#pragma unroll
        for (int o = 16; o > 0; o >>= 1)
            acc[e] += __shfl_xor_sync(0xffffffffu, acc[e], o);

    if (lane == 0) {
        float logit[NE];
#pragma unroll
        for (int e = 0; e < NE; e++) logit[e] = acc[e] + bg[e];

        float mx = logit[0];
#pragma unroll
        for (int e = 1; e < NE; e++) mx = fmaxf(mx, logit[e]);
        float s = 0.f, ex[NE];
#pragma unroll
        for (int e = 0; e < NE; e++) { ex[e] = expf(logit[e] - mx); s += ex[e]; }
        float inv = 1.f / s;
#pragma unroll
        for (int e = 0; e < NE; e++) g_gates[gwarp * NE + e] = ex[e] * inv;

        int i0 = 0;
#pragma unroll
        for (int e = 1; e < NE; e++) if (logit[e] > logit[i0]) i0 = e;
        int i1 = -1;
#pragma unroll
        for (int e = 0; e < NE; e++)
            if (e != i0 && (i1 < 0 || logit[e] > logit[i1])) i1 = e;

        float w0 = 1.f / (1.f + expf(logit[i1] - logit[i0]));
        g_topi[gwarp * 2 + 0] = i0;
        g_topi[gwarp * 2 + 1] = i1;
        g_topw[gwarp * 2 + 0] = w0;
        g_topw[gwarp * 2 + 1] = 1.f - w0;
    }
}

__global__ void route_kernel() {
    __shared__ int hist[RT_THREADS][NE];
    __shared__ int offs_sh[NE];
    __shared__ int counts_sh[NE];
    int tid = threadIdx.x;

    int h[NE];
#pragma unroll
    for (int e = 0; e < NE; e++) h[e] = 0;
    int t0 = tid * TOK_PER_TH;
    for (int i = 0; i < TOK_PER_TH; i++) {
        int t = t0 + i;
        h[g_topi[t * 2 + 0]]++;
        h[g_topi[t * 2 + 1]]++;
    }
#pragma unroll
    for (int e = 0; e < NE; e++) hist[tid][e] = h[e];
    __syncthreads();

    if (tid < NE) {
        int e = tid, s = 0;
        for (int j = 0; j < RT_THREADS; j++) {
            int v = hist[j][e];
            hist[j][e] = s;
            s += v;
        }
        counts_sh[e] = s;
        g_counts[e]  = s;
    }
    __syncthreads();

    if (tid == 0) {
        int off = 0;
        for (int e = 0; e < NE; e++) { offs_sh[e] = off; off += counts_sh[e]; }
    }
    __syncthreads();

    int base[NE];
#pragma unroll
    for (int e = 0; e < NE; e++) base[e] = offs_sh[e] + hist[tid][e];

    for (int i = 0; i < TOK_PER_TH; i++) {
        int t = t0 + i;
#pragma unroll
        for (int k = 0; k < TOPK; k++) {
            int e   = g_topi[t * 2 + k];
            int row = base[e]++;
            g_token_of_row[row] = t;
            g_row_of[t * 2 + k] = row;
        }
    }
}

// Fused per-expert usage mean + load-balance loss (single block, deterministic).
__global__ void usage_loss_kernel(float* __restrict__ out, int out_size) {
    __shared__ float s[256][NE];
    int tid = threadIdx.x;
    float acc[NE];
#pragma unroll
    for (int e = 0; e < NE; e++) acc[e] = 0.f;
    for (int t = tid; t < BTOK; t += 256) {
        const float* g = g_gates + (size_t)t * NE;
#pragma unroll
        for (int e = 0; e < NE; e++) acc[e] += g[e];
    }
#pragma unroll
    for (int e = 0; e < NE; e++) s[tid][e] = acc[e];
    __syncthreads();
    if (tid == 0) {
        float loss = 0.f;
        for (int e = 0; e < NE; e++) {
            float u = 0.f;
            for (int j = 0; j < 256; j++) u += s[j][e];
            u /= (float)BTOK;
            loss += u * u;
        }
        if (out_size > BTOK * DOUT) out[BTOK * DOUT] = (float)NE * loss;
    }
}

// ---------------- grouped GEMM: cp.async + HMMA, split-bf16 3-pass --------------
// Operands pre-split in global (bf16 hi/lo). cp.async 2-stage pipeline, no
// register staging. A smem [m][k] (non-trans ldsm), B smem [k][n] (trans ldsm).
// STAGE=1: A = g_x (gathered rows) -> g_h hi/lo (bf16x2), ReLU.
// STAGE=2: A = g_h (contiguous)    -> g_y (fp32).
template <int KD, int ND, int STAGE>
__global__ void __launch_bounds__(256, 2)
moe_gemm_cp(const float* __restrict__ bias) {
    int t = blockIdx.x;

    int e = 0, grow0 = 0, rows = 0;
    {
        int tileacc = 0, off = 0;
        bool found = false;
#pragma unroll
        for (int ee = 0; ee < NE; ee++) {
            int c  = g_counts[ee];
            int nt = (c + BM - 1) / BM;
            if (!found && t < tileacc + nt) {
                found = true;
                e     = ee;
                int rb = (t - tileacc) * BM;
                grow0 = off + rb;
                rows  = min(BM, c - rb);
            }
            tileacc += nt;
            off     += c;
        }
        if (!found) return;
    }
    int n0 = blockIdx.y * BN;

    extern __shared__ __align__(16) uint8_t dynsmem[];
    uint32_t sbase = smem_u32(dynsmem);

    int tid = threadIdx.x, wid = tid >> 5, lane = tid & 31;
    int warp_m = wid & 3;        // 0..3 -> m offset *32
    int warp_n = wid >> 2;       // 0..1 -> n offset *64

    // ---- cp.async source pointers ----
    int arow = tid >> 1, ahalf = tid & 1;           // A: 128 rows x 2 halves
    const uint32_t *Asrc_h, *Asrc_l;
    if (STAGE == 1) {
        int tok = (arow < rows) ? g_token_of_row[grow0 + arow] : g_token_of_row[grow0];
        Asrc_h = g_x_hi + (size_t)tok * (KD / 2);
        Asrc_l = g_x_lo + (size_t)tok * (KD / 2);
    } else {
        int r = min(grow0 + arow, MAXROWS - 1);
        Asrc_h = g_h_hi + (size_t)r * (KD / 2);
        Asrc_l = g_h_lo + (size_t)r * (KD / 2);
    }
    int bkrow = tid >> 3, bseg = tid & 7;           // B: 32 k-rows x 8 segs (x2)
    const uint32_t* Wh = (STAGE == 1 ? g_w1_hi : g_w2_hi)
                         + ((size_t)e * KD + bkrow) * (ND / 2) + n0 / 2 + bseg * 4;
    const uint32_t* Wl = (STAGE == 1 ? g_w1_lo : g_w2_lo)
                         + ((size_t)e * KD + bkrow) * (ND / 2) + n0 / 2 + bseg * 4;

    // ---- ldmatrix address bases ----
    uint32_t a_off = (uint32_t)(warp_m * 32 + (lane & 15)) * A_STRIDE
                   + (uint32_t)(lane >> 4) * 16;
    uint32_t b_off = (uint32_t)((lane & 7) + ((lane >> 3) & 1) * 8) * B_STRIDE
                   + (uint32_t)(warp_n * 64 + ((lane >> 4) & 1) * 8) * 2;

    float acc[2][8][4];
#pragma unroll
    for (int i = 0; i < 2; i++)
#pragma unroll
        for (int j = 0; j < 8; j++)
#pragma unroll
            for (int q = 0; q < 4; q++) acc[i][j][q] = 0.f;

    const int NCH = KD / BK;

    auto issue = [&](int it, int buf) {
        uint32_t base = sbase + (uint32_t)buf * BUF_BYTES;
        int k0 = it * BK;
        // A: row arow, half ahalf -> 2x16B per type
        uint32_t dA = base + (uint32_t)arow * A_STRIDE + (uint32_t)ahalf * 32;
        const uint32_t* sh = Asrc_h + (k0 >> 1) + ahalf * 8;
        const uint32_t* sl = Asrc_l + (k0 >> 1) + ahalf * 8;
        cp16(dA,               sh);
        cp16(dA + 16,          sh + 4);
        cp16(dA + A_REG,       sl);
        cp16(dA + A_REG + 16,  sl + 4);
        // B: k-row bkrow, segs bseg and bseg+8 per type
        uint32_t dB = base + 2 * A_REG + (uint32_t)bkrow * B_STRIDE + (uint32_t)bseg * 16;
        const uint32_t* bh = Wh + (size_t)k0 * (ND / 2);
        const uint32_t* bl = Wl + (size_t)k0 * (ND / 2);
        cp16(dB,                bh);
        cp16(dB + 128,          bh + 32);
        cp16(dB + B_REG,        bl);
        cp16(dB + B_REG + 128,  bl + 32);
        CP_COMMIT();
    };

    // prologue: 2 chunks in flight
    issue(0, 0);
    issue(1, 1);

    for (int it = 0; it < NCH; it++) {
        if (it + 1 < NCH) CP_WAIT1(); else CP_WAIT0();
        __syncthreads();

        uint32_t base = sbase + (uint32_t)(it & 1) * BUF_BYTES;
        uint32_t Ah = base, Al = base + A_REG;
        uint32_t Bh = base + 2 * A_REG, Bl = Bh + B_REG;

#pragma unroll
        for (int h = 0; h < 2; h++) {
            uint32_t fAh[2][4], fAl[2][4];
#pragma unroll
            for (int mi = 0; mi < 2; mi++) {
                uint32_t ad = a_off + (uint32_t)mi * (16 * A_STRIDE) + (uint32_t)h * 32;
                ldsm4(fAh[mi], Ah + ad);
                ldsm4(fAl[mi], Al + ad);
            }
#pragma unroll
            for (int n2 = 0; n2 < 4; n2++) {
                uint32_t bh[4], bl[4];
                uint32_t bd = b_off + (uint32_t)h * (16 * B_STRIDE) + (uint32_t)n2 * 32;
                ldsm4t(bh, Bh + bd);
                ldsm4t(bl, Bl + bd);
#pragma unroll
                for (int mi = 0; mi < 2; mi++) {
                    mma_bf16(acc[mi][2 * n2],     fAh[mi], bh[0], bh[1]);
                    mma_bf16(acc[mi][2 * n2 + 1], fAh[mi], bh[2], bh[3]);
                    mma_bf16(acc[mi][2 * n2],     fAh[mi], bl[0], bl[1]);
                    mma_bf16(acc[mi][2 * n2 + 1], fAh[mi], bl[2], bl[3]);
                    mma_bf16(acc[mi][2 * n2],     fAl[mi], bh[0], bh[1]);
                    mma_bf16(acc[mi][2 * n2 + 1], fAl[mi], bh[2], bh[3]);
                }
            }
        }
        __syncthreads();
        if (it + 2 < NCH) issue(it + 2, it & 1);
    }

    // ---- epilogue ----
#pragma unroll
    for (int mi = 0; mi < 2; mi++) {
        int m_lo = warp_m * 32 + mi * 16 + (lane >> 2);
#pragma unroll
        for (int ni = 0; ni < 8; ni++) {
            int ncol = warp_n * 64 + ni * 8 + 2 * (lane & 3);
            float b0 = bias[(size_t)e * ND + n0 + ncol];
            float b1 = bias[(size_t)e * ND + n0 + ncol + 1];
#pragma unroll
            for (int half = 0; half < 2; half++) {
                int m = m_lo + half * 8;
                if (m < rows) {
                    float v0 = acc[mi][ni][2 * half]     + b0;
                    float v1 = acc[mi][ni][2 * half + 1] + b1;
                    size_t grow = (size_t)(grow0 + m);
                    if (STAGE == 1) {
                        v0 = fmaxf(v0, 0.f);
                        v1 = fmaxf(v1, 0.f);
                        uint32_t hw, lw;
                        split2(v0, v1, hw, lw);
                        size_t hidx = grow * (ND / 2) + (size_t)(n0 + ncol) / 2;
                        g_h_hi[hidx] = hw;
                        g_h_lo[hidx] = lw;
                    } else {
                        float* cp = g_y + grow * ND + n0 + ncol;
                        cp[0] = v0;
                        cp[1] = v1;
                    }
                }
            }
        }
    }
}

// out[t] = w0 * y[row0] + w1 * y[row1]
__global__ void combine_kernel(float* __restrict__ out) {
    int t = blockIdx.x;
    int r0 = g_row_of[t * 2 + 0];
    int r1 = g_row_of[t * 2 + 1];
    float w0 = g_topw[t * 2 + 0];
    float w1 = g_topw[t * 2 + 1];
    const float4* y0 = (const float4*)(g_y + (size_t)r0 * DOUT);
    const float4* y1 = (const float4*)(g_y + (size_t)r1 * DOUT);
    float4* o = (float4*)(out + (size_t)t * DOUT);
    for (int j = threadIdx.x; j < DOUT / 4; j += blockDim.x) {
        float4 a = y0[j], b = y1[j];
        float4 r;
        r.x = w0 * a.x + w1 * b.x;
        r.y = w0 * a.y + w1 * b.y;
        r.z = w0 * a.z + w1 * b.z;
        r.w = w0 * a.w + w1 * b.w;
        o[j] = r;
    }
}

// ---------------- launch ---------------------------------------------------------

extern "C" void kernel_launch(void* const* d_in, const int* in_sizes, int n_in,
                              void* d_out, int out_size) {
    const float *x = 0, *Wg = 0, *bg = 0, *W1 = 0, *b1 = 0, *W2 = 0, *b2 = 0;
    for (int i = 0; i < n_in; i++) {
        const float* p = (const float*)d_in[i];
        switch (in_sizes[i]) {
            case BTOK * DIN:        x  = p; break;                        // 4194304
            case NE:                bg = p; break;                        // 8
            case NE * DHID:         b1 = p; break;                        // 32768
            case NE * DIN * DHID:   if (!W1) W1 = p; else W2 = p; break;  // 33554432
            case DIN * NE:          if (!Wg) Wg = p; else b2 = p; break;  // 8192
            default: break;
        }
    }
    if (!(x && Wg && bg && W1 && b1 && W2 && b2)) {
        x  = (const float*)d_in[0]; Wg = (const float*)d_in[1];
        bg = (const float*)d_in[2]; W1 = (const float*)d_in[3];
        b1 = (const float*)d_in[4]; W2 = (const float*)d_in[5];
        b2 = (const float*)d_in[6];
    }
    float* out = (float*)d_out;

    cudaFuncSetAttribute(moe_gemm_cp<DIN, DHID, 1>,
                         cudaFuncAttributeMaxDynamicSharedMemorySize, SMEM_TOTAL);
    cudaFuncSetAttribute(moe_gemm_cp<DHID, DOUT, 2>,
                         cudaFuncAttributeMaxDynamicSharedMemorySize, SMEM_TOTAL);

    split_all_kernel<<<(ALLPAIRS + 255) / 256, 256>>>(x, W1, W2);   // launch 1
    gating_kernel<<<BTOK / 8, 256>>>(x, Wg, bg);                    // launch 2
    route_kernel<<<1, RT_THREADS>>>();                              // launch 3

    moe_gemm_cp<DIN, DHID, 1>                                       // launch 4 (ncu)
        <<<dim3(MAXTILES, DHID / BN), 256, SMEM_TOTAL>>>(b1);

    usage_loss_kernel<<<1, 256>>>(out, out_size);                   // launch 5

    moe_gemm_cp<DHID, DOUT, 2>                                      // launch 6
        <<<dim3(MAXTILES, DOUT / BN), 256, SMEM_TOTAL>>>(b2);

    combine_kernel<<<BTOK, 256>>>(out);                             // launch 7
}

// round 11
// speedup vs baseline: 3.2280x; 2.2413x over previous
#include <cuda_runtime.h>
#include <cuda_fp16.h>
#include <math.h>
#include <stdint.h>

// ---------------- problem constants -------------------------------------------
#define BTOK   4096
#define DIN    1024
#define DHID   4096
#define DOUT   1024
#define NE     8
#define TOPK   2
#define MAXROWS (BTOK * TOPK)          // 8192 grouped rows, always exact
#define BM     128
#define BN     128
#define BK     32
#define MAXTILES (MAXROWS / BM + NE)   // 72 worst-case m-tiles

#define RT_THREADS 256
#define TOK_PER_TH (BTOK / RT_THREADS) // 16

// ---------------- smem tile geometry --------------------------------------------
#define A_STRIDE 80                     // bytes per A row: 32 fp16 (64B) + 16B pad
#define B_STRIDE 272                    // bytes per B k-row: 128 fp16 (256B) + 16B pad
#define A_REG (BM * A_STRIDE)           // 10240
#define B_REG (BK * B_STRIDE)           // 8704
#define STG_BYTES (A_REG + B_REG)       // 18944 per stage
#define NSTAGE 4
#define SMEM_TOTAL (NSTAGE * STG_BYTES) // 75776

// quad counts for the fused fp32->fp16 conversion (4 floats -> 2 words each)
#define XQUADS (BTOK * (size_t)DIN / 4)
#define WQUADS ((size_t)NE * DIN * DHID / 4)
#define ALLQUADS (XQUADS + 2 * WQUADS)       // 17,825,792

// ---------------- device scratch (device-code-only access!) --------------------
__device__ uint32_t g_xh[BTOK * (size_t)(DIN / 2)];          // fp16x2
__device__ uint32_t g_w1h[(size_t)NE * DIN * DHID / 2];
__device__ uint32_t g_w2h[(size_t)NE * DHID * DOUT / 2];
__device__ uint32_t g_hh[MAXROWS * (size_t)(DHID / 2)];
__device__ float    g_y[MAXROWS * (size_t)DOUT];
__device__ float    g_gates[BTOK * NE];
__device__ float    g_topw[BTOK * TOPK];
__device__ int      g_topi[BTOK * TOPK];
__device__ int      g_counts[NE];
__device__ int      g_token_of_row[MAXROWS];
__device__ int      g_row_of[BTOK * TOPK];

// ---------------- helpers -------------------------------------------------------
__device__ __forceinline__ uint32_t smem_u32(const void* p) {
    uint32_t a;
    asm("{ .reg .u64 t; cvta.to.shared.u64 t, %1; cvt.u32.u64 %0, t; }"
        : "=r"(a) : "l"(p));
    return a;
}

__device__ __forceinline__ void ldsm4(uint32_t* r, uint32_t addr) {
    asm volatile("ldmatrix.sync.aligned.m8n8.x4.shared.b16 {%0,%1,%2,%3}, [%4];"
                 : "=r"(r[0]), "=r"(r[1]), "=r"(r[2]), "=r"(r[3]) : "r"(addr));
}

__device__ __forceinline__ void ldsm4t(uint32_t* r, uint32_t addr) {
    asm volatile("ldmatrix.sync.aligned.m8n8.x4.trans.shared.b16 {%0,%1,%2,%3}, [%4];"
                 : "=r"(r[0]), "=r"(r[1]), "=r"(r[2]), "=r"(r[3]) : "r"(addr));
}

__device__ __forceinline__ void mma_f16(float* c, const uint32_t* a,
                                        uint32_t b0, uint32_t b1) {
    asm volatile(
        "mma.sync.aligned.m16n8k16.row.col.f32.f16.f16.f32 "
        "{%0,%1,%2,%3}, {%4,%5,%6,%7}, {%8,%9}, {%0,%1,%2,%3};"
        : "+f"(c[0]), "+f"(c[1]), "+f"(c[2]), "+f"(c[3])
        : "r"(a[0]), "r"(a[1]), "r"(a[2]), "r"(a[3]), "r"(b0), "r"(b1));
}

__device__ __forceinline__ void cp16(uint32_t dst, const void* src) {
    asm volatile("cp.async.cg.shared.global [%0], [%1], 16;"
                 :: "r"(dst), "l"(src));
}
#define CP_COMMIT() asm volatile("cp.async.commit_group;" ::: "memory")
#define CP_WAIT2()  asm volatile("cp.async.wait_group 2;" ::: "memory")
#define CP_WAIT1()  asm volatile("cp.async.wait_group 1;" ::: "memory")
#define CP_WAIT0()  asm volatile("cp.async.wait_group 0;" ::: "memory")

__device__ __forceinline__ uint32_t h2u(__half2 h) {
    return *reinterpret_cast<uint32_t*>(&h);
}

// ---------------- fused convert: x, W1, W2 -> fp16 ------------------------------
__global__ void convert_all_kernel(const float* __restrict__ x,
                                   const float* __restrict__ W1,
                                   const float* __restrict__ W2) {
    size_t p = (size_t)blockIdx.x * blockDim.x + threadIdx.x;
    if (p >= ALLQUADS) return;
    const float* src;
    uint32_t* dst;
    size_t q;
    if (p < XQUADS)               { q = p;                    src = x;  dst = g_xh;  }
    else if (p < XQUADS + WQUADS) { q = p - XQUADS;           src = W1; dst = g_w1h; }
    else                          { q = p - XQUADS - WQUADS;  src = W2; dst = g_w2h; }
    float4 v = ((const float4*)src)[q];
    dst[q * 2 + 0] = h2u(__floats2half2_rn(v.x, v.y));
    dst[q * 2 + 1] = h2u(__floats2half2_rn(v.z, v.w));
}

// ---------------- gating / routing / loss --------------------------------------

__global__ void gating_kernel(const float* __restrict__ x,
                              const float* __restrict__ Wg,
                              const float* __restrict__ bg) {
    int gwarp = (blockIdx.x * blockDim.x + threadIdx.x) >> 5;
    int lane  = threadIdx.x & 31;
    if (gwarp >= BTOK) return;
    const float* xr = x + (size_t)gwarp * DIN;

    float acc[NE];
#pragma unroll
    for (int e = 0; e < NE; e++) acc[e] = 0.f;

    for (int i = lane; i < DIN; i += 32) {
        float xv = xr[i];
        const float4* wg4 = (const float4*)(Wg + (size_t)i * NE);
        float4 w0 = wg4[0];
        float4 w1 = wg4[1];
        acc[0] += xv * w0.x; acc[1] += xv * w0.y;
        acc[2] += xv * w0.z; acc[3] += xv * w0.w;
        acc[4] += xv * w1.x; acc[5] += xv * w1.y;
        acc[6] += xv * w1.z; acc[7] += xv * w1.w;
    }
#pragma unroll
    for (int e = 0; e < NE; e++)
#pragma unroll
        for (int o = 16; o > 0; o >>= 1)
            acc[e] += __shfl_xor_sync(0xffffffffu, acc[e], o);

    if (lane == 0) {
        float logit[NE];
#pragma unroll
        for (int e = 0; e < NE; e++) logit[e] = acc[e] + bg[e];

        float mx = logit[0];
#pragma unroll
        for (int e = 1; e < NE; e++) mx = fmaxf(mx, logit[e]);
        float s = 0.f, ex[NE];
#pragma unroll
        for (int e = 0; e < NE; e++) { ex[e] = expf(logit[e] - mx); s += ex[e]; }
        float inv = 1.f / s;
#pragma unroll
        for (int e = 0; e < NE; e++) g_gates[gwarp * NE + e] = ex[e] * inv;

        int i0 = 0;
#pragma unroll
        for (int e = 1; e < NE; e++) if (logit[e] > logit[i0]) i0 = e;
        int i1 = -1;
#pragma unroll
        for (int e = 0; e < NE; e++)
            if (e != i0 && (i1 < 0 || logit[e] > logit[i1])) i1 = e;

        float w0 = 1.f / (1.f + expf(logit[i1] - logit[i0]));
        g_topi[gwarp * 2 + 0] = i0;
        g_topi[gwarp * 2 + 1] = i1;
        g_topw[gwarp * 2 + 0] = w0;
        g_topw[gwarp * 2 + 1] = 1.f - w0;
    }
}

__global__ void route_kernel() {
    __shared__ int hist[RT_THREADS][NE];
    __shared__ int offs_sh[NE];
    __shared__ int counts_sh[NE];
    int tid = threadIdx.x;

    int h[NE];
#pragma unroll
    for (int e = 0; e < NE; e++) h[e] = 0;
    int t0 = tid * TOK_PER_TH;
    for (int i = 0; i < TOK_PER_TH; i++) {
        int t = t0 + i;
        h[g_topi[t * 2 + 0]]++;
        h[g_topi[t * 2 + 1]]++;
    }
#pragma unroll
    for (int e = 0; e < NE; e++) hist[tid][e] = h[e];
    __syncthreads();

    if (tid < NE) {
        int e = tid, s = 0;
        for (int j = 0; j < RT_THREADS; j++) {
            int v = hist[j][e];
            hist[j][e] = s;
            s += v;
        }
        counts_sh[e] = s;
        g_counts[e]  = s;
    }
    __syncthreads();

    if (tid == 0) {
        int off = 0;
        for (int e = 0; e < NE; e++) { offs_sh[e] = off; off += counts_sh[e]; }
    }
    __syncthreads();

    int base[NE];
#pragma unroll
    for (int e = 0; e < NE; e++) base[e] = offs_sh[e] + hist[tid][e];

    for (int i = 0; i < TOK_PER_TH; i++) {
        int t = t0 + i;
#pragma unroll
        for (int k = 0; k < TOPK; k++) {
            int e   = g_topi[t * 2 + k];
            int row = base[e]++;
            g_token_of_row[row] = t;
            g_row_of[t * 2 + k] = row;
        }
    }
}

// Fused per-expert usage mean + load-balance loss (single block, deterministic).
__global__ void usage_loss_kernel(float* __restrict__ out, int out_size) {
    __shared__ float s[256][NE];
    int tid = threadIdx.x;
    float acc[NE];
#pragma unroll
    for (int e = 0; e < NE; e++) acc[e] = 0.f;
    for (int t = tid; t < BTOK; t += 256) {
        const float* g = g_gates + (size_t)t * NE;
#pragma unroll
        for (int e = 0; e < NE; e++) acc[e] += g[e];
    }
#pragma unroll
    for (int e = 0; e < NE; e++) s[tid][e] = acc[e];
    __syncthreads();
    if (tid == 0) {
        float loss = 0.f;
        for (int e = 0; e < NE; e++) {
            float u = 0.f;
            for (int j = 0; j < 256; j++) u += s[j][e];
            u /= (float)BTOK;
            loss += u * u;
        }
        if (out_size > BTOK * DOUT) out[BTOK * DOUT] = (float)NE * loss;
    }
}

// ---------------- grouped GEMM: cp.async (4-stage) + fp16 HMMA ------------------
// STAGE=1: A = g_xh (gathered rows) -> g_hh (fp16x2), ReLU.
// STAGE=2: A = g_hh (contiguous)    -> g_y (fp32).
template <int KD, int ND, int STAGE>
__global__ void __launch_bounds__(256, 2)
moe_gemm_f16(const float* __restrict__ bias) {
    int t = blockIdx.x;

    int e = 0, grow0 = 0, rows = 0;
    {
        int tileacc = 0, off = 0;
        bool found = false;
#pragma unroll
        for (int ee = 0; ee < NE; ee++) {
            int c  = g_counts[ee];
            int nt = (c + BM - 1) / BM;
            if (!found && t < tileacc + nt) {
                found = true;
                e     = ee;
                int rb = (t - tileacc) * BM;
                grow0 = off + rb;
                rows  = min(BM, c - rb);
            }
            tileacc += nt;
            off     += c;
        }
        if (!found) return;
    }
    int n0 = blockIdx.y * BN;

    extern __shared__ __align__(16) uint8_t dynsmem[];
    uint32_t sbase = smem_u32(dynsmem);

    int tid = threadIdx.x, wid = tid >> 5, lane = tid & 31;
    int warp_m = wid & 3;        // 0..3 -> m offset *32
    int warp_n = wid >> 2;       // 0..1 -> n offset *64

    // ---- cp.async source pointers ----
    int arow = tid >> 1, ahalf = tid & 1;           // A: 128 rows x 2 halves
    const uint32_t* Asrc;
    if (STAGE == 1) {
        int tok = (arow < rows) ? g_token_of_row[grow0 + arow] : g_token_of_row[grow0];
        Asrc = g_xh + (size_t)tok * (KD / 2);
    } else {
        int r = min(grow0 + arow, MAXROWS - 1);
        Asrc = g_hh + (size_t)r * (KD / 2);
    }
    int bkrow = tid >> 3, bseg = tid & 7;           // B: 32 k-rows x 8 segs x2
    const uint32_t* Wsrc = (STAGE == 1 ? g_w1h : g_w2h)
                           + ((size_t)e * KD + bkrow) * (ND / 2) + n0 / 2 + bseg * 4;

    // ---- ldmatrix address bases ----
    uint32_t a_off = (uint32_t)(warp_m * 32 + (lane & 15)) * A_STRIDE
                   + (uint32_t)(lane >> 4) * 16;
    uint32_t b_off = (uint32_t)((lane & 7) + ((lane >> 3) & 1) * 8) * B_STRIDE
                   + (uint32_t)(warp_n * 64 + ((lane >> 4) & 1) * 8) * 2;

    float acc[2][8][4];
#pragma unroll
    for (int i = 0; i < 2; i++)
#pragma unroll
        for (int j = 0; j < 8; j++)
#pragma unroll
            for (int q = 0; q < 4; q++) acc[i][j][q] = 0.f;

    const int NCH = KD / BK;

    auto issue = [&](int it) {
        uint32_t base = sbase + (uint32_t)(it & (NSTAGE - 1)) * STG_BYTES;
        int k0 = it * BK;
        // A: row arow, half ahalf -> 2x16B
        uint32_t dA = base + (uint32_t)arow * A_STRIDE + (uint32_t)ahalf * 32;
        const uint32_t* sa = Asrc + (k0 >> 1) + ahalf * 8;
        cp16(dA,      sa);
        cp16(dA + 16, sa + 4);
        // B: k-row bkrow, segs bseg and bseg+8
        uint32_t dB = base + A_REG + (uint32_t)bkrow * B_STRIDE + (uint32_t)bseg * 16;
        const uint32_t* sb = Wsrc + (size_t)k0 * (ND / 2);
        cp16(dB,       sb);
        cp16(dB + 128, sb + 32);
        CP_COMMIT();
    };

    // prologue: 3 chunks in flight
    issue(0);
    issue(1);
    issue(2);

    for (int it = 0; it < NCH; it++) {
        // wait for chunk it (tail-aware)
        if (it < NCH - 2)       CP_WAIT2();
        else if (it == NCH - 2) CP_WAIT1();
        else                    CP_WAIT0();
        __syncthreads();
        // refill the slot consumed 2 syncs ago (race-free after the sync above)
        if (it + 3 < NCH) issue(it + 3);

        uint32_t base = sbase + (uint32_t)(it & (NSTAGE - 1)) * STG_BYTES;
        uint32_t Ab = base, Bb = base + A_REG;

#pragma unroll
        for (int h = 0; h < 2; h++) {
            uint32_t fA[2][4];
#pragma unroll
            for (int mi = 0; mi < 2; mi++) {
                uint32_t ad = a_off + (uint32_t)mi * (16 * A_STRIDE) + (uint32_t)h * 32;
                ldsm4(fA[mi], Ab + ad);
            }
#pragma unroll
            for (int n2 = 0; n2 < 4; n2++) {
                uint32_t fB[4];
                uint32_t bd = b_off + (uint32_t)h * (16 * B_STRIDE) + (uint32_t)n2 * 32;
                ldsm4t(fB, Bb + bd);
#pragma unroll
                for (int mi = 0; mi < 2; mi++) {
                    mma_f16(acc[mi][2 * n2],     fA[mi], fB[0], fB[1]);
                    mma_f16(acc[mi][2 * n2 + 1], fA[mi], fB[2], fB[3]);
                }
            }
        }
    }

    // ---- epilogue ----
#pragma unroll
    for (int mi = 0; mi < 2; mi++) {
        int m_lo = warp_m * 32 + mi * 16 + (lane >> 2);
#pragma unroll
        for (int ni = 0; ni < 8; ni++) {
            int ncol = warp_n * 64 + ni * 8 + 2 * (lane & 3);
            float b0 = bias[(size_t)e * ND + n0 + ncol];
            float b1 = bias[(size_t)e * ND + n0 + ncol + 1];
#pragma unroll
            for (int half = 0; half < 2; half++) {
                int m = m_lo + half * 8;
                if (m < rows) {
                    float v0 = acc[mi][ni][2 * half]     + b0;
                    float v1 = acc[mi][ni][2 * half + 1] + b1;
                    size_t grow = (size_t)(grow0 + m);
                    if (STAGE == 1) {
                        v0 = fmaxf(v0, 0.f);
                        v1 = fmaxf(v1, 0.f);
                        g_hh[grow * (ND / 2) + (size_t)(n0 + ncol) / 2] =
                            h2u(__floats2half2_rn(v0, v1));
                    } else {
                        float* cp = g_y + grow * ND + n0 + ncol;
                        cp[0] = v0;
                        cp[1] = v1;
                    }
                }
            }
        }
    }
}

// out[t] = w0 * y[row0] + w1 * y[row1]
__global__ void combine_kernel(float* __restrict__ out) {
    int t = blockIdx.x;
    int r0 = g_row_of[t * 2 + 0];
    int r1 = g_row_of[t * 2 + 1];
    float w0 = g_topw[t * 2 + 0];
    float w1 = g_topw[t * 2 + 1];
    const float4* y0 = (const float4*)(g_y + (size_t)r0 * DOUT);
    const float4* y1 = (const float4*)(g_y + (size_t)r1 * DOUT);
    float4* o = (float4*)(out + (size_t)t * DOUT);
    for (int j = threadIdx.x; j < DOUT / 4; j += blockDim.x) {
        float4 a = y0[j], b = y1[j];
        float4 r;
        r.x = w0 * a.x + w1 * b.x;
        r.y = w0 * a.y + w1 * b.y;
        r.z = w0 * a.z + w1 * b.z;
        r.w = w0 * a.w + w1 * b.w;
        o[j] = r;
    }
}

// ---------------- launch ---------------------------------------------------------

extern "C" void kernel_launch(void* const* d_in, const int* in_sizes, int n_in,
                              void* d_out, int out_size) {
    const float *x = 0, *Wg = 0, *bg = 0, *W1 = 0, *b1 = 0, *W2 = 0, *b2 = 0;
    for (int i = 0; i < n_in; i++) {
        const float* p = (const float*)d_in[i];
        switch (in_sizes[i]) {
            case BTOK * DIN:        x  = p; break;                        // 4194304
            case NE:                bg = p; break;                        // 8
            case NE * DHID:         b1 = p; break;                        // 32768
            case NE * DIN * DHID:   if (!W1) W1 = p; else W2 = p; break;  // 33554432
            case DIN * NE:          if (!Wg) Wg = p; else b2 = p; break;  // 8192
            default: break;
        }
    }
    if (!(x && Wg && bg && W1 && b1 && W2 && b2)) {
        x  = (const float*)d_in[0]; Wg = (const float*)d_in[1];
        bg = (const float*)d_in[2]; W1 = (const float*)d_in[3];
        b1 = (const float*)d_in[4]; W2 = (const float*)d_in[5];
        b2 = (const float*)d_in[6];
    }
    float* out = (float*)d_out;

    cudaFuncSetAttribute(moe_gemm_f16<DIN, DHID, 1>,
                         cudaFuncAttributeMaxDynamicSharedMemorySize, SMEM_TOTAL);
    cudaFuncSetAttribute(moe_gemm_f16<DHID, DOUT, 2>,
                         cudaFuncAttributeMaxDynamicSharedMemorySize, SMEM_TOTAL);

    convert_all_kernel<<<(int)((ALLQUADS + 255) / 256), 256>>>(x, W1, W2); // 1
    gating_kernel<<<BTOK / 8, 256>>>(x, Wg, bg);                           // 2
    route_kernel<<<1, RT_THREADS>>>();                                     // 3

    moe_gemm_f16<DIN, DHID, 1>                                             // 4 (ncu)
        <<<dim3(MAXTILES, DHID / BN), 256, SMEM_TOTAL>>>(b1);

    usage_loss_kernel<<<1, 256>>>(out, out_size);                          // 5

    moe_gemm_f16<DHID, DOUT, 2>                                            // 6
        <<<dim3(MAXTILES, DOUT / BN), 256, SMEM_TOTAL>>>(b2);

    combine_kernel<<<BTOK, 256>>>(out);                                    // 7
}